// round 4
// baseline (speedup 1.0000x reference)
#include <cuda_runtime.h>

#define B_   64
#define NI   2048
#define NO   32
#define DDO  16
#define DDI  16
#define OD   512
#define NSEG 148          // n-tiles are strided over 148 segments (2 CTAs share a segment)
#define THREADS 256

typedef unsigned long long ull;

// ---- per-CTA shared memory layout (floats) ----
#define WT_PITCH 516
#define WT_SIZE  (DDI * WT_PITCH)        // 8256 per buffer
#define XD_OFF   (2 * WT_SIZE)           // dup (x,x) float2 [i][32] -> 1024 floats
#define WS_OFF   (XD_OFF + 1024)         // sWs[16][33]              ->  528
#define CT_OFF   (WS_OFF + 528)          // sCT[32][36]              -> 1152
#define SMEM_FLOATS (CT_OFF + 1152)      // 19216 floats = 76864 B  (x2 CTAs = 150KB/SM)

// column swizzle for the 32-wide x-dup table
#define XCOL(b) ((((b) & 3) << 3) | ((b) >> 2))

// partials: [seg][o][b 0..63][d]   (the two half-CTAs write disjoint b ranges)
__device__ float g_part[(size_t)NSEG * OD * B_];

__device__ __forceinline__ void fma2(ull& d, ull a, ull b) {
    asm("fma.rn.f32x2 %0, %1, %2, %0;" : "+l"(d) : "l"(a), "l"(b));
}
__device__ __forceinline__ ull mul2(ull a, ull b) {
    ull r; asm("mul.rn.f32x2 %0, %1, %2;" : "=l"(r) : "l"(a), "l"(b)); return r;
}
__device__ __forceinline__ ull pack_dup(float a) {
    ull r; asm("mov.b64 %0, {%1, %1};" : "=l"(r) : "f"(a)); return r;
}
__device__ __forceinline__ float2 unpk(ull a) {
    float2 r; asm("mov.b64 {%0, %1}, %2;" : "=f"(r.x), "=f"(r.y) : "l"(a)); return r;
}
__device__ __forceinline__ void cpa4(unsigned dst, const float* src) {
    asm volatile("cp.async.ca.shared.global [%0], [%1], 4;" :: "r"(dst), "l"(src));
}
__device__ __forceinline__ void cpa_commit() { asm volatile("cp.async.commit_group;"); }
__device__ __forceinline__ void cpa_wait0()  { asm volatile("cp.async.wait_group 0;"); }

// transposing stage of W tile n into smem buffer at sbase ([i][od] layout)
__device__ __forceinline__ void stage_w_async(const float* __restrict__ W, int n,
                                              unsigned sbase, int tid)
{
    const float* Wg = W + (size_t)n * (OD * DDI);
    #pragma unroll
    for (int k = 0; k < 32; k++) {
        int g  = tid + k * THREADS;          // coalesced gmem over [od][i]
        int od = g >> 4;
        int i  = g & 15;
        cpa4(sbase + 4u * (unsigned)(i * WT_PITCH + od), Wg + g);
    }
    cpa_commit();
}

extern "C" __global__ void __launch_bounds__(THREADS, 2)
capsule_main(const float* __restrict__ X, const float* __restrict__ W)
{
    extern __shared__ float sm[];
    float2* sXD2 = (float2*)(sm + XD_OFF);
    float*  sWs  = sm + WS_OFF;
    float*  sCT  = sm + CT_OFF;

    const int tid  = threadIdx.x;
    const int lane = tid & 31;
    const int wid  = tid >> 5;
    const int o    = tid >> 3;               // 0..31
    const int bg   = tid & 7;                // 4 local batches b0..b0+3
    const int b0   = 4 * bg;
    const int seg  = blockIdx.x >> 1;        // 0..147
    const int half = blockIdx.x & 1;         // batch half (b offset 32*half)
    const unsigned smem_u = (unsigned)__cvta_generic_to_shared(sm);

    ull acc[8][4];
    #pragma unroll
    for (int p = 0; p < 8; p++)
        #pragma unroll
        for (int j = 0; j < 4; j++) acc[p][j] = 0ull;

    // ---- prologue ----
    int n = seg;
    stage_w_async(W, n, smem_u, tid);
    float4 xv;
    if (tid < 128)
        xv = *(const float4*)(X + ((size_t)(half * 32 + (tid >> 2)) * NI + n) * DDI
                              + (tid & 3) * 4);

    int cur = 0;
    for (; n < NI; n += NSEG) {
        float* sWT = sm + cur * WT_SIZE;

        cpa_wait0();
        __syncthreads();

        // ---- stage x duplicated (x,x) at swizzled column ----
        if (tid < 128) {
            int bl = tid >> 2;               // local batch 0..31
            int i0 = (tid & 3) * 4;
            int bc = XCOL(bl);
            sXD2[(i0 + 0) * 32 + bc] = make_float2(xv.x, xv.x);
            sXD2[(i0 + 1) * 32 + bc] = make_float2(xv.y, xv.y);
            sXD2[(i0 + 2) * 32 + bc] = make_float2(xv.z, xv.z);
            sXD2[(i0 + 3) * 32 + bc] = make_float2(xv.w, xv.w);
        }
        // ---- Wsum[o][i]: thread (i = tid&15, o2 = tid>>4) does o = 2*o2, 2*o2+1 ----
        {
            int ii = tid & 15, o2 = tid >> 4;
            #pragma unroll
            for (int t = 0; t < 2; t++) {
                const float* r = sWT + ii * WT_PITCH + (2 * o2 + t) * 16;
                float4 a = *(const float4*)(r);
                float4 b = *(const float4*)(r + 4);
                float4 c = *(const float4*)(r + 8);
                float4 d = *(const float4*)(r + 12);
                sWs[ii * 33 + 2 * o2 + t] =
                    ((a.x + a.y) + (a.z + a.w)) + ((b.x + b.y) + (b.z + b.w)) +
                    ((c.x + c.y) + (c.z + c.w)) + ((d.x + d.y) + (d.z + d.w));
            }
        }
        // ---- prefetch n+NSEG ----
        {
            int n2 = n + NSEG;
            if (n2 < NI) {
                stage_w_async(W, n2, smem_u + 4u * (unsigned)((cur ^ 1) * WT_SIZE), tid);
                if (tid < 128)
                    xv = *(const float4*)(X + ((size_t)(half * 32 + (tid >> 2)) * NI + n2) * DDI
                                          + (tid & 3) * 4);
            }
        }
        __syncthreads();

        // ---- routing: warp wid handles local b = wid + 8*bb, lane = o ----
        #pragma unroll
        for (int bb = 0; bb < 4; bb++) {
            int bl = wid + 8 * bb;
            int bc = XCOL(bl);
            float h = 0.f;
            #pragma unroll
            for (int i = 0; i < DDI; i++)
                h = fmaf(sWs[i * 33 + lane], sXD2[i * 32 + bc].x, h);

            float b1 = h * 0.03125f;
            float m = b1;
            #pragma unroll
            for (int off = 16; off; off >>= 1)
                m = fmaxf(m, __shfl_xor_sync(0xffffffffu, m, off));
            float e = __expf(b1 - m);
            float s = e;
            #pragma unroll
            for (int off = 16; off; off >>= 1)
                s += __shfl_xor_sync(0xffffffffu, s, off);
            float b2 = fmaf(__fdividef(e, s), h, b1);

            m = b2;
            #pragma unroll
            for (int off = 16; off; off >>= 1)
                m = fmaxf(m, __shfl_xor_sync(0xffffffffu, m, off));
            e = __expf(b2 - m);
            s = e;
            #pragma unroll
            for (int off = 16; off; off >>= 1)
                s += __shfl_xor_sync(0xffffffffu, s, off);

            sCT[lane * 36 + bl] = __fdividef(e, s);
        }
        __syncthreads();

        // ---- main contraction: acc[p][j] += (W[2p],W[2p+1]) * (c2*x) ----
        {
            float4 cv = *(const float4*)(sCT + o * 36 + b0);
            ull c2d[4];
            c2d[0] = pack_dup(cv.x); c2d[1] = pack_dup(cv.y);
            c2d[2] = pack_dup(cv.z); c2d[3] = pack_dup(cv.w);

            #pragma unroll
            for (int i = 0; i < DDI; i++) {
                const ull* xrow = (const ull*)(sXD2 + i * 32);
                ull xs[4];
                #pragma unroll
                for (int j = 0; j < 4; j++)
                    xs[j] = mul2(xrow[j * 8 + bg], c2d[j]);

                const float* wrow = sWT + i * WT_PITCH + o * 16;
                #pragma unroll
                for (int jj = 0; jj < 4; jj++) {
                    ulonglong2 w4 = *(const ulonglong2*)(wrow + 4 * jj);
                    #pragma unroll
                    for (int j = 0; j < 4; j++) {
                        fma2(acc[2 * jj + 0][j], w4.x, xs[j]);
                        fma2(acc[2 * jj + 1][j], w4.y, xs[j]);
                    }
                }
            }
        }
        cur ^= 1;
    }

    // ---- writeout: g_part[seg][o][b][d] ----
    float* gp = g_part + (size_t)seg * (OD * B_) + o * 1024 + (half * 32 + b0) * 16;
    #pragma unroll
    for (int j = 0; j < 4; j++) {
        #pragma unroll
        for (int q = 0; q < 4; q++) {
            float2 a0 = unpk(acc[2 * q + 0][j]);
            float2 a1 = unpk(acc[2 * q + 1][j]);
            *(float4*)(gp + j * 16 + 4 * q) = make_float4(a0.x, a0.y, a1.x, a1.y);
        }
    }
}

// grid 512 x 256: warp-per-32-float2s, 8 warps split the 148 partials
extern "C" __global__ void __launch_bounds__(256)
capsule_reduce(float* __restrict__ out)
{
    __shared__ float2 red[8][32];
    const int lane = threadIdx.x & 31;
    const int w    = threadIdx.x >> 5;
    const int e    = blockIdx.x * 32 + lane;

    const int cnt   = 18 + (w < 4 ? 1 : 0);
    const int start = w * 18 + (w < 4 ? w : 4);

    const float2* p = ((const float2*)g_part) + e;
    float sx = 0.f, sy = 0.f;
    #pragma unroll
    for (int k = 0; k < 19; k++) {
        if (k < cnt) {
            float2 v = p[(size_t)(start + k) * 16384];
            sx += v.x; sy += v.y;
        }
    }
    red[w][lane] = make_float2(sx, sy);
    __syncthreads();

    if (w == 0) {
        sx = 0.f; sy = 0.f;
        #pragma unroll
        for (int k = 0; k < 8; k++) { float2 v = red[k][lane]; sx += v.x; sy += v.y; }

        float q = sx * sx + sy * sy;
        q += __shfl_xor_sync(0xffffffffu, q, 1);
        q += __shfl_xor_sync(0xffffffffu, q, 2);
        q += __shfl_xor_sync(0xffffffffu, q, 4);

        float scale = q / ((1.f + q) * sqrtf(q + 1e-7f));
        int o = e >> 9, b = (e >> 3) & 63, dp = e & 7;
        *(float2*)(out + (size_t)b * (NO * DDO) + o * 16 + 2 * dp) =
            make_float2(scale * sx, scale * sy);
    }
}

// window-shift dummies so ncu (-s 5 -c 1) lands on capsule_main (index 1 mod 4)
extern "C" __global__ void capsule_nopA() {}
extern "C" __global__ void capsule_nopB() {}

extern "C" void kernel_launch(void* const* d_in, const int* in_sizes, int n_in,
                              void* d_out, int out_size)
{
    const float* a = (const float*)d_in[0];
    const float* c = (const float*)d_in[1];
    const float *X, *W;
    if (in_sizes[0] == B_ * NI * DDI) { X = a; W = c; }
    else                              { X = c; W = a; }

    size_t smem = (size_t)SMEM_FLOATS * sizeof(float);
    cudaFuncSetAttribute(capsule_main,
                         cudaFuncAttributeMaxDynamicSharedMemorySize, (int)smem);

    capsule_nopA<<<1, 1>>>();
    capsule_main<<<2 * NSEG, THREADS, smem>>>(X, W);
    capsule_nopB<<<1, 1>>>();
    capsule_reduce<<<512, 256>>>((float*)d_out);
}

// round 6
// speedup vs baseline: 1.1465x; 1.1465x over previous
#include <cuda_runtime.h>

#define B_   64
#define NI   2048
#define NO   32
#define DDO  16
#define DDI  16
#define OD   512
#define NBLK 148
#define THREADS 512

typedef unsigned long long ull;

// ---- shared memory layout (floats) ----
#define WT_PITCH 516                     // [i][od] row pitch
#define WT_SIZE  (DDI * WT_PITCH)        // 8256
#define XD_OFF   WT_SIZE                 // dup (x,x) float2 [i][64] -> 2048 floats
#define WS_OFF   (XD_OFF + 2048)         // sWs[16][33]              ->  528
#define CT_OFF   (WS_OFF + 528)          // sCT[32][68]              -> 2176
#define SMEM_FLOATS (CT_OFF + 2176)      // 13008 floats = 52032 B

#define XCOL(b) ((((b) & 3) << 4) | ((b) >> 2))

// partials: [seg][o][b][d]  (float2 view: e = o*512 + b*8 + dp, 16384 per seg)
__device__ float    g_part[(size_t)NBLK * OD * B_];
__device__ unsigned g_cnt = 0;           // monotone grid-sync ticket (never reset)

__device__ __forceinline__ void fma2(ull& d, ull a, ull b) {
    asm("fma.rn.f32x2 %0, %1, %2, %0;" : "+l"(d) : "l"(a), "l"(b));
}
__device__ __forceinline__ ull mul2(ull a, ull b) {
    ull r; asm("mul.rn.f32x2 %0, %1, %2;" : "=l"(r) : "l"(a), "l"(b)); return r;
}
__device__ __forceinline__ ull pack_dup(float a) {
    ull r; asm("mov.b64 %0, {%1, %1};" : "=l"(r) : "f"(a)); return r;
}
__device__ __forceinline__ float2 unpk(ull a) {
    float2 r; asm("mov.b64 {%0, %1}, %2;" : "=f"(r.x), "=f"(r.y) : "l"(a)); return r;
}

extern "C" __global__ void __launch_bounds__(THREADS, 1)
capsule_main(const float* __restrict__ X, const float* __restrict__ W,
             float* __restrict__ out)
{
    extern __shared__ float sm[];
    float*  sWT  = sm;                       // W transposed: [i][od]
    float2* sXD2 = (float2*)(sm + XD_OFF);
    float*  sWs  = sm + WS_OFF;
    float*  sCT  = sm + CT_OFF;

    const int tid  = threadIdx.x;
    const int lane = tid & 31;
    const int wid  = tid >> 5;
    const int o    = tid >> 4;
    const int bg   = tid & 15;
    const int b0   = 4 * bg;

    ull acc[8][4];
    #pragma unroll
    for (int p = 0; p < 8; p++)
        #pragma unroll
        for (int j = 0; j < 4; j++) acc[p][j] = 0ull;

    // ---- prologue prefetch ----
    int n = blockIdx.x;
    float4 wv[4];
    {
        const float4* Wg = (const float4*)(W + (size_t)n * (OD * DDI));
        #pragma unroll
        for (int k = 0; k < 4; k++) wv[k] = Wg[tid + k * THREADS];
    }
    float4 xv;
    if (tid < 256)
        xv = *(const float4*)(X + ((size_t)(tid >> 2) * NI + n) * DDI + (tid & 3) * 4);

    for (int it = 0; n < NI; it++, n += NBLK) {
        if (it) __syncthreads();

        // ---- stage W transposed [i][od] ----
        #pragma unroll
        for (int k = 0; k < 4; k++) {
            int g  = tid + k * THREADS;
            int od = g >> 2;
            int i0 = (g & 3) * 4;
            sWT[(i0 + 0) * WT_PITCH + od] = wv[k].x;
            sWT[(i0 + 1) * WT_PITCH + od] = wv[k].y;
            sWT[(i0 + 2) * WT_PITCH + od] = wv[k].z;
            sWT[(i0 + 3) * WT_PITCH + od] = wv[k].w;
        }
        // ---- stage x duplicated (x,x) at swizzled column ----
        if (tid < 256) {
            int b  = tid >> 2;
            int i0 = (tid & 3) * 4;
            int bc = XCOL(b);
            sXD2[(i0 + 0) * 64 + bc] = make_float2(xv.x, xv.x);
            sXD2[(i0 + 1) * 64 + bc] = make_float2(xv.y, xv.y);
            sXD2[(i0 + 2) * 64 + bc] = make_float2(xv.z, xv.z);
            sXD2[(i0 + 3) * 64 + bc] = make_float2(xv.w, xv.w);
        }
        __syncthreads();

        // ---- prefetch n+NBLK into regs (overlaps Wsum/routing/contraction) ----
        {
            int n2 = n + NBLK;
            if (n2 < NI) {
                const float4* Wg = (const float4*)(W + (size_t)n2 * (OD * DDI));
                #pragma unroll
                for (int k = 0; k < 4; k++) wv[k] = Wg[tid + k * THREADS];
                if (tid < 256)
                    xv = *(const float4*)(X + ((size_t)(tid >> 2) * NI + n2) * DDI + (tid & 3) * 4);
            }
        }

        // ---- Wsum[o][i] = sum_d W[n,o,d,i] ----
        {
            int oo = tid >> 4, ii = tid & 15;
            const float* r = sWT + ii * WT_PITCH + oo * 16;
            float4 a = *(const float4*)(r);
            float4 b = *(const float4*)(r + 4);
            float4 c = *(const float4*)(r + 8);
            float4 d = *(const float4*)(r + 12);
            sWs[ii * 33 + oo] = ((a.x + a.y) + (a.z + a.w)) + ((b.x + b.y) + (b.z + b.w))
                              + ((c.x + c.y) + (c.z + c.w)) + ((d.x + d.y) + (d.z + d.w));
        }
        __syncthreads();

        // ---- routing (no max-subtraction; softmax is shift-invariant, |h| small) ----
        #pragma unroll
        for (int bb = 0; bb < 4; bb++) {
            int b  = wid + 16 * bb;
            int bc = XCOL(b);
            float h = 0.f;
            #pragma unroll
            for (int i = 0; i < DDI; i++)
                h = fmaf(sWs[i * 33 + lane], sXD2[i * 64 + bc].x, h);

            float b1 = h * 0.03125f;
            float e1 = __expf(b1);
            float s1 = e1;
            #pragma unroll
            for (int off = 16; off; off >>= 1)
                s1 += __shfl_xor_sync(0xffffffffu, s1, off);
            float b2 = fmaf(__fdividef(e1, s1), h, b1);

            float e2 = __expf(b2);
            float s2 = e2;
            #pragma unroll
            for (int off = 16; off; off >>= 1)
                s2 += __shfl_xor_sync(0xffffffffu, s2, off);

            sCT[lane * 68 + b] = __fdividef(e2, s2);
        }
        __syncthreads();

        // ---- main contraction ----
        {
            float4 cv = *(const float4*)(sCT + o * 68 + b0);
            ull c2d[4];
            c2d[0] = pack_dup(cv.x); c2d[1] = pack_dup(cv.y);
            c2d[2] = pack_dup(cv.z); c2d[3] = pack_dup(cv.w);

            #pragma unroll
            for (int i = 0; i < DDI; i++) {
                const ull* xrow = (const ull*)(sXD2 + i * 64);
                ull xs[4];
                #pragma unroll
                for (int j = 0; j < 4; j++)
                    xs[j] = mul2(xrow[j * 16 + bg], c2d[j]);

                const float* wrow = sWT + i * WT_PITCH + o * 16;
                #pragma unroll
                for (int jj = 0; jj < 4; jj++) {
                    ulonglong2 w4 = *(const ulonglong2*)(wrow + 4 * jj);
                    #pragma unroll
                    for (int j = 0; j < 4; j++) {
                        fma2(acc[2 * jj + 0][j], w4.x, xs[j]);
                        fma2(acc[2 * jj + 1][j], w4.y, xs[j]);
                    }
                }
            }
        }
    }

    // ---- writeout partials: g_part[seg][o][b][d] ----
    float* gp = g_part + (size_t)blockIdx.x * (OD * B_) + o * 1024 + b0 * 16;
    #pragma unroll
    for (int j = 0; j < 4; j++) {
        #pragma unroll
        for (int q = 0; q < 4; q++) {
            float2 a0 = unpk(acc[2 * q + 0][j]);
            float2 a1 = unpk(acc[2 * q + 1][j]);
            *(float4*)(gp + j * 16 + 4 * q) = make_float4(a0.x, a0.y, a1.x, a1.y);
        }
    }

    // ---- software grid barrier (monotone ticket; graph-replay safe) ----
    __threadfence();
    __syncthreads();
    if (tid == 0) {
        unsigned t = atomicAdd(&g_cnt, 1u);
        unsigned target = (t / NBLK + 1u) * NBLK;
        while ((int)(*(volatile unsigned*)&g_cnt) - (int)target < 0) {}
        __threadfence();                 // acquire: order cross-block g_part reads
    }
    __syncthreads();

    // ---- fused reduce + squash: 4 threads per float2-output, 37 segs each ----
    {
        const int g = blockIdx.x * THREADS + tid;
        if (g < 65536) {
            const int e    = g >> 2;          // float2 output index 0..16383
            const int part = g & 3;           // seg residue

            const float2* p = ((const float2*)g_part) + (size_t)part * 16384 + e;
            float sx = 0.f, sy = 0.f;
            #pragma unroll
            for (int k = 0; k < 37; k++) {    // segs part, part+4, ..., part+144
                float2 v;
                const float2* q = p + (size_t)(4 * k) * 16384;
                v.x = __ldcg(&q->x); v.y = __ldcg(&q->y);
                sx += v.x; sy += v.y;
            }
            // combine the 4 parts (lanes 4k..4k+3 share e)
            sx += __shfl_xor_sync(0xffffffffu, sx, 1);
            sx += __shfl_xor_sync(0xffffffffu, sx, 2);
            sy += __shfl_xor_sync(0xffffffffu, sy, 1);
            sy += __shfl_xor_sync(0xffffffffu, sy, 2);

            // sum s_d^2 over the 8 dp-groups: xor 4,8,16 picks exactly one lane
            // per group (orbit of bits 2..4) -> already Σ_d s_d², no replication
            float qv = sx * sx + sy * sy;
            qv += __shfl_xor_sync(0xffffffffu, qv, 4);
            qv += __shfl_xor_sync(0xffffffffu, qv, 8);
            qv += __shfl_xor_sync(0xffffffffu, qv, 16);
            float s2 = qv;

            if (part == 0) {
                float scale = s2 / ((1.f + s2) * sqrtf(s2 + 1e-7f));
                int oo = e >> 9, bb = (e >> 3) & 63, dp = e & 7;
                *(float2*)(out + (size_t)bb * (NO * DDO) + oo * 16 + 2 * dp) =
                    make_float2(scale * sx, scale * sy);
            }
        }
    }
}

extern "C" void kernel_launch(void* const* d_in, const int* in_sizes, int n_in,
                              void* d_out, int out_size)
{
    const float* a = (const float*)d_in[0];
    const float* c = (const float*)d_in[1];
    const float *X, *W;
    if (in_sizes[0] == B_ * NI * DDI) { X = a; W = c; }
    else                              { X = c; W = a; }

    size_t smem = (size_t)SMEM_FLOATS * sizeof(float);
    cudaFuncSetAttribute(capsule_main,
                         cudaFuncAttributeMaxDynamicSharedMemorySize, (int)smem);
    capsule_main<<<NBLK, THREADS, smem>>>(X, W, (float*)d_out);
}